// round 15
// baseline (speedup 1.0000x reference)
#include <cuda_runtime.h>
#include <cstdint>

#define HS 128
#define WS 128
#define NPIX 16384
#define BATCH 8
#define CDIM 192
#define C3 576
#define HEADS 8
#define CD 24

// ---------------- scratch (device globals; no allocation allowed) ----------------
__device__ __align__(128) float g_qkv0[(size_t)BATCH * C3 * NPIX];   // after 1x1 conv
__device__ __align__(128) float g_v[(size_t)BATCH * CDIM * NPIX];    // v after dw conv
__device__ __align__(128) float g_G[BATCH * HEADS * CD * CD];
__device__ __align__(128) float g_QN[BATCH * HEADS * CD];
__device__ __align__(128) float g_KN[BATCH * HEADS * CD];
__device__ __align__(128) float g_W[BATCH * HEADS * CD * CD];
__device__ __align__(128) float g_M[BATCH * CDIM * CDIM];

// ---------------- init ----------------
__global__ void init_stats_kernel() {
    int stride = gridDim.x * blockDim.x;
    int i = blockIdx.x * blockDim.x + threadIdx.x;
    for (; i < BATCH * HEADS * CD * CD; i += stride) g_G[i] = 0.f;
    int j = blockIdx.x * blockDim.x + threadIdx.x;
    for (; j < BATCH * HEADS * CD; j += stride) { g_QN[j] = 0.f; g_KN[j] = 0.f; }
}

// ---------------- SGEMM (R10 structure, explicit batch): C[b] = A @ B[b] + bias ----------------
// MODE 0: A = w_qkv (576x192), B = x[b] (192xN), C = g_qkv0[b]
// MODE 1: A = g_M[b] (192x192), B = g_v[b] (192xN), C = out[b]
// BM=64, BN=128, BK=16, TM=TN=8, 128 threads
template<int MODE>
__global__ __launch_bounds__(128) void gemm_kernel(
    const float* __restrict__ Aext, const float* __restrict__ Bext,
    const float* __restrict__ bias, float* __restrict__ Cext, int b)
{
    constexpr int K = CDIM;
    const float* Ab = (MODE == 0) ? Aext : (g_M + (size_t)b * CDIM * CDIM);
    const float* Bb = (MODE == 0) ? (Bext + (size_t)b * CDIM * NPIX)
                                  : (g_v + (size_t)b * CDIM * NPIX);
    float* Cb = (MODE == 0) ? (g_qkv0 + (size_t)b * C3 * NPIX)
                            : (Cext + (size_t)b * CDIM * NPIX);

    const int n0 = blockIdx.x * 128;
    const int m0 = blockIdx.y * 64;

    __shared__ __align__(16) float As[16][64];
    __shared__ __align__(16) float Bs[16][128];

    const int tid = threadIdx.x;
    const int tx = tid & 15;        // 0..15 -> n groups of 8
    const int ty = tid >> 4;        // 0..7  -> m groups of 8

    const int arow = tid >> 1;            // 0..63
    const int acol = (tid & 1) * 8;       // 0 or 8

    float acc[8][8];
#pragma unroll
    for (int i = 0; i < 8; i++)
#pragma unroll
        for (int j = 0; j < 8; j++) acc[i][j] = 0.f;

    for (int k0 = 0; k0 < K; k0 += 16) {
        float4 av0 = *(const float4*)&Ab[(size_t)(m0 + arow) * K + k0 + acol];
        float4 av1 = *(const float4*)&Ab[(size_t)(m0 + arow) * K + k0 + acol + 4];
        As[acol + 0][arow] = av0.x;
        As[acol + 1][arow] = av0.y;
        As[acol + 2][arow] = av0.z;
        As[acol + 3][arow] = av0.w;
        As[acol + 4][arow] = av1.x;
        As[acol + 5][arow] = av1.y;
        As[acol + 6][arow] = av1.z;
        As[acol + 7][arow] = av1.w;
#pragma unroll
        for (int i = 0; i < 4; i++) {
            int f = tid + i * 128;
            int kk = f >> 5;                  // 0..15
            int c4 = (f & 31) * 4;            // 0..124
            *(float4*)&Bs[kk][c4] = *(const float4*)&Bb[(size_t)(k0 + kk) * NPIX + n0 + c4];
        }
        __syncthreads();
#pragma unroll
        for (int kk = 0; kk < 16; kk++) {
            float ra[8], rb[8];
            *(float4*)&ra[0] = *(const float4*)&As[kk][ty * 8];
            *(float4*)&ra[4] = *(const float4*)&As[kk][ty * 8 + 4];
            *(float4*)&rb[0] = *(const float4*)&Bs[kk][tx * 8];
            *(float4*)&rb[4] = *(const float4*)&Bs[kk][tx * 8 + 4];
#pragma unroll
            for (int i = 0; i < 8; i++)
#pragma unroll
                for (int j = 0; j < 8; j++) acc[i][j] += ra[i] * rb[j];
        }
        __syncthreads();
    }

#pragma unroll
    for (int i = 0; i < 8; i++) {
        int o = m0 + ty * 8 + i;
        float bo = bias[o];
        size_t base = (size_t)o * NPIX + n0 + tx * 8;
        float4 v0 = make_float4(acc[i][0] + bo, acc[i][1] + bo, acc[i][2] + bo, acc[i][3] + bo);
        float4 v1 = make_float4(acc[i][4] + bo, acc[i][5] + bo, acc[i][6] + bo, acc[i][7] + bo);
        *(float4*)&Cb[base] = v0;
        *(float4*)&Cb[base + 4] = v1;
    }
}

// ---------------- dw conv (3x3) + Gram/norm reduction + v write ----------------
// grid: (64 tiles of 16x16, HEADS, 1) per batch, 256 threads.
// R14 structure: register double-buffered halo prefetch hides global latency.
#define DW_QS 0                      // 256*25 floats
#define DW_KS 6400                   // 256*25 floats
#define DW_HALO 12800                // 4 * 360 floats = 1440
#define DW_SMEM_FLOATS 14240         // * 4 = 56960 bytes

__global__ __launch_bounds__(256) void dw_gram_kernel(
    const float* __restrict__ w_dw, const float* __restrict__ b_dw, int b)
{
    extern __shared__ float ds[];
    float* qs = ds + DW_QS;          // [pix 0..255][25]
    float* ks2 = ds + DW_KS;
    float* halo = ds + DW_HALO;      // [slot][18 rows][20 cols]

    const int h = blockIdx.y, tile = blockIdx.x;
    const int r0 = (tile >> 3) * 16, c0 = (tile & 7) * 16;
    const int tid = threadIdx.x;
    const int slot = tid >> 6;           // 0..3 (warp-pair uniform)
    const int s = tid & 63;
    const int sr = s >> 2;               // 0..15 output row
    const int sc = (s & 3) * 4;          // 0,4,8,12 output col base
    const size_t bq = (size_t)b * C3 * NPIX;

    // per-thread staging elements: t = tid + j*256, t < 1296 (= 4*324)
    float pre[6];
#pragma unroll
    for (int j = 0; j < 6; j++) {
        int t = tid + j * 256;
        if (t < 1296) {
            int p = t / 324, e = t % 324;
            int hr = e / 18, hc = e % 18;
            int pi = p;                       // it = 0
            int which = pi / 24, c = pi % 24;
            int ch = which * CDIM + h * CD + c;
            int Rg = r0 - 1 + hr, Cg = c0 - 1 + hc;
            float vv = 0.f;
            if (Rg >= 0 && Rg < HS && Cg >= 0 && Cg < WS)
                vv = g_qkv0[bq + (size_t)ch * NPIX + (size_t)Rg * WS + Cg];
            pre[j] = vv;
        }
    }

    for (int it = 0; it < 18; it++) {
        __syncthreads();                  // previous halo fully consumed
#pragma unroll
        for (int j = 0; j < 6; j++) {
            int t = tid + j * 256;
            if (t < 1296) {
                int p = t / 324, e = t % 324;
                halo[p * 360 + (e / 18) * 20 + (e % 18)] = pre[j];
            }
        }
        __syncthreads();
        // prefetch next iteration's halo (overlaps compute below)
        if (it + 1 < 18) {
#pragma unroll
            for (int j = 0; j < 6; j++) {
                int t = tid + j * 256;
                if (t < 1296) {
                    int p = t / 324, e = t % 324;
                    int hr = e / 18, hc = e % 18;
                    int pi = (it + 1) * 4 + p;
                    int which = pi / 24, c = pi % 24;
                    int ch = which * CDIM + h * CD + c;
                    int Rg = r0 - 1 + hr, Cg = c0 - 1 + hc;
                    float vv = 0.f;
                    if (Rg >= 0 && Rg < HS && Cg >= 0 && Cg < WS)
                        vv = g_qkv0[bq + (size_t)ch * NPIX + (size_t)Rg * WS + Cg];
                    pre[j] = vv;
                }
            }
        }

        const int pi = it * 4 + slot;
        const int which = pi / 24, c = pi % 24;
        const int ch = which * CDIM + h * CD + c;
        const float* wp = w_dw + ch * 9;
        const float* hp = halo + slot * 360;
        float bz = __ldg(&b_dw[ch]);
        float s0 = bz, s1 = bz, s2 = bz, s3 = bz;
#pragma unroll
        for (int r = 0; r < 3; r++) {
            float4 a = *(const float4*)(hp + (sr + r) * 20 + sc);
            float4 bv = *(const float4*)(hp + (sr + r) * 20 + sc + 4);
            float w0 = __ldg(&wp[r * 3 + 0]);
            float w1 = __ldg(&wp[r * 3 + 1]);
            float w2 = __ldg(&wp[r * 3 + 2]);
            s0 += a.x * w0 + a.y * w1 + a.z * w2;
            s1 += a.y * w0 + a.z * w1 + a.w * w2;
            s2 += a.z * w0 + a.w * w1 + bv.x * w2;
            s3 += a.w * w0 + bv.x * w1 + bv.y * w2;
        }
        const int p = sr * 16 + sc;
        if (which == 0) {
            qs[(p + 0) * 25 + c] = s0;
            qs[(p + 1) * 25 + c] = s1;
            qs[(p + 2) * 25 + c] = s2;
            qs[(p + 3) * 25 + c] = s3;
        } else if (which == 1) {
            ks2[(p + 0) * 25 + c] = s0;
            ks2[(p + 1) * 25 + c] = s1;
            ks2[(p + 2) * 25 + c] = s2;
            ks2[(p + 3) * 25 + c] = s3;
        } else {
            float* vp = g_v + (size_t)b * CDIM * NPIX + (size_t)(h * CD + c) * NPIX
                        + (size_t)(r0 + sr) * WS + (c0 + sc);
            *(float4*)vp = make_float4(s0, s1, s2, s3);
        }
    }
    __syncthreads();

    const int bh = b * HEADS + h;
    if (tid < 192) {
        const int cc = tid >> 3;
        const int db = (tid & 7) * 3;
        float a0 = 0.f, a1 = 0.f, a2 = 0.f;
        for (int p = 0; p < 256; p++) {
            float qv = qs[p * 25 + cc];
            a0 += qv * ks2[p * 25 + db];
            a1 += qv * ks2[p * 25 + db + 1];
            a2 += qv * ks2[p * 25 + db + 2];
        }
        float* Gp = g_G + (size_t)bh * CD * CD + cc * CD + db;
        atomicAdd(&Gp[0], a0);
        atomicAdd(&Gp[1], a1);
        atomicAdd(&Gp[2], a2);
    } else if (tid < 216) {
        const int c = tid - 192;
        float a = 0.f;
        for (int p = 0; p < 256; p++) { float qv = qs[p * 25 + c]; a += qv * qv; }
        atomicAdd(&g_QN[bh * CD + c], a);
    } else if (tid < 240) {
        const int c = tid - 216;
        float a = 0.f;
        for (int p = 0; p < 256; p++) { float kv = ks2[p * 25 + c]; a += kv * kv; }
        atomicAdd(&g_KN[bh * CD + c], a);
    }
}

// ---------------- attn: norms + 4x top-k sparse softmax via rank selection -> g_W ----------------
__global__ __launch_bounds__(32) void attn_kernel(
    const float* __restrict__ temp,
    const float* __restrict__ a1, const float* __restrict__ a2,
    const float* __restrict__ a3, const float* __restrict__ a4)
{
    const int bh = blockIdx.x;
    const int h = bh % HEADS;
    const int c = threadIdx.x;
    if (c >= CD) return;
    float attn[CD];
    float qn = fmaxf(sqrtf(g_QN[bh * CD + c]), 1e-12f);
    const float tmp = temp[h];
#pragma unroll
    for (int j = 0; j < CD; j++) {
        float kn = fmaxf(sqrtf(g_KN[bh * CD + j]), 1e-12f);
        attn[j] = g_G[(size_t)bh * CD * CD + c * CD + j] * tmp / (qn * kn);
    }
    float m = attn[0];
#pragma unroll
    for (int j = 1; j < CD; j++) m = fmaxf(m, attn[j]);
    int rank[CD];
#pragma unroll
    for (int j = 0; j < CD; j++) {
        int r = 0;
#pragma unroll
        for (int i = 0; i < CD; i++) {
            bool gt = (attn[i] > attn[j]) || (attn[i] == attn[j] && i < j);
            r += gt ? 1 : 0;
        }
        rank[j] = r;
    }
    float e[CD];
    float sum0 = 0.f, sum1 = 0.f, sum2 = 0.f, sum3 = 0.f;
#pragma unroll
    for (int j = 0; j < CD; j++) {
        e[j] = expf(attn[j] - m);
        if (rank[j] < 12) sum0 += e[j];
        if (rank[j] < 16) sum1 += e[j];
        if (rank[j] < 18) sum2 += e[j];
        if (rank[j] < 19) sum3 += e[j];
    }
    const float r0 = a1[0] / sum0, r1 = a2[0] / sum1, r2 = a3[0] / sum2, r3 = a4[0] / sum3;
    float* Wp = g_W + (size_t)bh * CD * CD + c * CD;
#pragma unroll
    for (int j = 0; j < CD; j++) {
        float w = 0.f;
        if (rank[j] < 12) w += r0 * e[j];
        if (rank[j] < 16) w += r1 * e[j];
        if (rank[j] < 18) w += r2 * e[j];
        if (rank[j] < 19) w += r3 * e[j];
        Wp[j] = w;
    }
}

// ---------------- fold: M[b][o][h*24+d] = sum_c wproj[o][h*24+c] * W[b,h][c][d] ----------------
__global__ __launch_bounds__(256) void fold_kernel(const float* __restrict__ wproj)
{
    const int b = blockIdx.x, s = blockIdx.y;
    const int t = threadIdx.x;
    const int o = s * 32 + (t >> 3);
    const int hh = t & 7;
    const float* Wp = g_W + ((size_t)(b * HEADS + hh)) * CD * CD;
    float acc[CD];
#pragma unroll
    for (int d = 0; d < CD; d++) acc[d] = 0.f;
#pragma unroll
    for (int c = 0; c < CD; c++) {
        float w = __ldg(&wproj[o * CDIM + hh * CD + c]);
#pragma unroll
        for (int d = 0; d < CD; d++) acc[d] += w * __ldg(&Wp[c * CD + d]);
    }
    float* Mo = g_M + (size_t)b * CDIM * CDIM + (size_t)o * CDIM + hh * CD;
#pragma unroll
    for (int d = 0; d < CD; d++) Mo[d] = acc[d];
}

// ---------------- launch ----------------
extern "C" void kernel_launch(void* const* d_in, const int* in_sizes, int n_in,
                              void* d_out, int out_size)
{
    const float* x      = (const float*)d_in[0];
    const float* w_qkv  = (const float*)d_in[1];
    const float* b_qkv  = (const float*)d_in[2];
    const float* w_dw   = (const float*)d_in[3];
    const float* b_dw   = (const float*)d_in[4];
    const float* w_proj = (const float*)d_in[5];
    const float* b_proj = (const float*)d_in[6];
    const float* temp   = (const float*)d_in[7];
    const float* a1     = (const float*)d_in[8];
    const float* a2     = (const float*)d_in[9];
    const float* a3     = (const float*)d_in[10];
    const float* a4     = (const float*)d_in[11];
    float* out = (float*)d_out;

    cudaFuncSetAttribute(dw_gram_kernel, cudaFuncAttributeMaxDynamicSharedMemorySize, DW_SMEM_FLOATS * 4);

    init_stats_kernel<<<64, 256>>>();

    // Interleaved per batch: GEMM1(b) then dw_gram(b) — qkv0[b] slice (38 MB)
    // stays resident in L2 between producer and consumer.
    for (int b = 0; b < BATCH; b++) {
        gemm_kernel<0><<<dim3(NPIX / 128, C3 / 64, 1), 128>>>(w_qkv, x, b_qkv, nullptr, b);
        dw_gram_kernel<<<dim3(64, HEADS, 1), 256, DW_SMEM_FLOATS * 4>>>(w_dw, b_dw, b);
    }

    // attention weights + fold
    attn_kernel<<<BATCH * HEADS, 32>>>(temp, a1, a2, a3, a4);
    fold_kernel<<<dim3(BATCH, 6), 256>>>(w_proj);

    // out[b] = g_M[b] @ g_v[b] + b_proj
    for (int b = 0; b < BATCH; b++)
        gemm_kernel<1><<<dim3(NPIX / 128, CDIM / 64, 1), 128>>>(nullptr, nullptr, b_proj, out, b);
}

// round 16
// speedup vs baseline: 1.2257x; 1.2257x over previous
#include <cuda_runtime.h>
#include <cstdint>

#define HS 128
#define WS 128
#define NPIX 16384
#define BATCH 8
#define CDIM 192
#define C3 576
#define HEADS 8
#define CD 24

// ---------------- scratch (device globals; no allocation allowed) ----------------
__device__ __align__(128) float g_qkv0[(size_t)BATCH * C3 * NPIX];   // after 1x1 conv
__device__ __align__(128) float g_v[(size_t)BATCH * CDIM * NPIX];    // v after dw conv
__device__ __align__(128) float g_G[BATCH * HEADS * CD * CD];
__device__ __align__(128) float g_QN[BATCH * HEADS * CD];
__device__ __align__(128) float g_KN[BATCH * HEADS * CD];
__device__ __align__(128) float g_W[BATCH * HEADS * CD * CD];
__device__ __align__(128) float g_M[BATCH * CDIM * CDIM];

// ---------------- init ----------------
__global__ void init_stats_kernel() {
    int stride = gridDim.x * blockDim.x;
    int i = blockIdx.x * blockDim.x + threadIdx.x;
    for (; i < BATCH * HEADS * CD * CD; i += stride) g_G[i] = 0.f;
    int j = blockIdx.x * blockDim.x + threadIdx.x;
    for (; j < BATCH * HEADS * CD; j += stride) { g_QN[j] = 0.f; g_KN[j] = 0.f; }
}

// ---------------- SGEMM, conflict-free split fragments: C[b] = A @ B[b] + bias ----------------
// MODE 0: A = w_qkv (576x192), B = x[b] (192xN), C = g_qkv0[b]
// MODE 1: A = g_M[b] (192x192), B = g_v[b] (192xN), C = out[b]
// BM=64, BN=128, BK=16, TM=TN=8 (as 2x4 split halves), 128 threads.
// Fragment LDS at 16B stride: lanes/phase hit 8 distinct banks (was 2-way conflicted).
template<int MODE>
__global__ __launch_bounds__(128) void gemm_kernel(
    const float* __restrict__ Aext, const float* __restrict__ Bext,
    const float* __restrict__ bias, float* __restrict__ Cext)
{
    constexpr int K = CDIM;
    const int b = blockIdx.z;
    const float* Ab = (MODE == 0) ? Aext : (g_M + (size_t)b * CDIM * CDIM);
    const float* Bb = (MODE == 0) ? (Bext + (size_t)b * CDIM * NPIX)
                                  : (g_v + (size_t)b * CDIM * NPIX);
    float* Cb = (MODE == 0) ? (g_qkv0 + (size_t)b * C3 * NPIX)
                            : (Cext + (size_t)b * CDIM * NPIX);

    const int n0 = blockIdx.x * 128;
    const int m0 = blockIdx.y * 64;

    __shared__ __align__(16) float As[16][64];
    __shared__ __align__(16) float Bs[16][128];

    const int tid = threadIdx.x;
    const int tx = tid & 15;        // 0..15 -> n quads
    const int ty = tid >> 4;        // 0..7  -> m quads

    const int arow = tid >> 1;            // 0..63
    const int acol = (tid & 1) * 8;       // 0 or 8

    float acc[8][8];
#pragma unroll
    for (int i = 0; i < 8; i++)
#pragma unroll
        for (int j = 0; j < 8; j++) acc[i][j] = 0.f;

    for (int k0 = 0; k0 < K; k0 += 16) {
        float4 av0 = *(const float4*)&Ab[(size_t)(m0 + arow) * K + k0 + acol];
        float4 av1 = *(const float4*)&Ab[(size_t)(m0 + arow) * K + k0 + acol + 4];
        As[acol + 0][arow] = av0.x;
        As[acol + 1][arow] = av0.y;
        As[acol + 2][arow] = av0.z;
        As[acol + 3][arow] = av0.w;
        As[acol + 4][arow] = av1.x;
        As[acol + 5][arow] = av1.y;
        As[acol + 6][arow] = av1.z;
        As[acol + 7][arow] = av1.w;
#pragma unroll
        for (int i = 0; i < 4; i++) {
            int f = tid + i * 128;
            int kk = f >> 5;                  // 0..15
            int c4 = (f & 31) * 4;            // 0..124
            *(float4*)&Bs[kk][c4] = *(const float4*)&Bb[(size_t)(k0 + kk) * NPIX + n0 + c4];
        }
        __syncthreads();
#pragma unroll
        for (int kk = 0; kk < 16; kk++) {
            float ra[8], rb[8];
            // split halves at 16B stride: conflict-free banks
            *(float4*)&ra[0] = *(const float4*)&As[kk][ty * 4];
            *(float4*)&ra[4] = *(const float4*)&As[kk][32 + ty * 4];
            *(float4*)&rb[0] = *(const float4*)&Bs[kk][tx * 4];
            *(float4*)&rb[4] = *(const float4*)&Bs[kk][64 + tx * 4];
#pragma unroll
            for (int i = 0; i < 8; i++)
#pragma unroll
                for (int j = 0; j < 8; j++) acc[i][j] += ra[i] * rb[j];
        }
        __syncthreads();
    }

    // epilogue: row half mh in {0,1} -> m0 + mh*32 + ty*4 + i;
    // col half nh in {0,1} -> n0 + nh*64 + tx*4 (+j)
#pragma unroll
    for (int mh = 0; mh < 2; mh++) {
#pragma unroll
        for (int i = 0; i < 4; i++) {
            int o = m0 + mh * 32 + ty * 4 + i;
            float bo = bias[o];
            size_t base = (size_t)o * NPIX + n0;
            int ai = mh * 4 + i;
            float4 v0 = make_float4(acc[ai][0] + bo, acc[ai][1] + bo, acc[ai][2] + bo, acc[ai][3] + bo);
            float4 v1 = make_float4(acc[ai][4] + bo, acc[ai][5] + bo, acc[ai][6] + bo, acc[ai][7] + bo);
            *(float4*)&Cb[base + tx * 4] = v0;
            *(float4*)&Cb[base + 64 + tx * 4] = v1;
        }
    }
}

// ---------------- dw conv (3x3) + Gram/norm reduction + v write (R14-verbatim) ----------------
#define DW_QS 0                      // 256*25 floats
#define DW_KS 6400                   // 256*25 floats
#define DW_HALO 12800                // 4 * 360 floats = 1440
#define DW_SMEM_FLOATS 14240         // * 4 = 56960 bytes

__global__ __launch_bounds__(256) void dw_gram_kernel(
    const float* __restrict__ w_dw, const float* __restrict__ b_dw)
{
    extern __shared__ float ds[];
    float* qs = ds + DW_QS;          // [pix 0..255][25]
    float* ks2 = ds + DW_KS;
    float* halo = ds + DW_HALO;      // [slot][18 rows][20 cols]

    const int b = blockIdx.z, h = blockIdx.y, tile = blockIdx.x;
    const int r0 = (tile >> 3) * 16, c0 = (tile & 7) * 16;
    const int tid = threadIdx.x;
    const int slot = tid >> 6;           // 0..3 (warp-pair uniform)
    const int s = tid & 63;
    const int sr = s >> 2;               // 0..15 output row
    const int sc = (s & 3) * 4;          // 0,4,8,12 output col base
    const size_t bq = (size_t)b * C3 * NPIX;

    float pre[6];
#pragma unroll
    for (int j = 0; j < 6; j++) {
        int t = tid + j * 256;
        if (t < 1296) {
            int p = t / 324, e = t % 324;
            int hr = e / 18, hc = e % 18;
            int pi = p;                       // it = 0
            int which = pi / 24, c = pi % 24;
            int ch = which * CDIM + h * CD + c;
            int Rg = r0 - 1 + hr, Cg = c0 - 1 + hc;
            float vv = 0.f;
            if (Rg >= 0 && Rg < HS && Cg >= 0 && Cg < WS)
                vv = g_qkv0[bq + (size_t)ch * NPIX + (size_t)Rg * WS + Cg];
            pre[j] = vv;
        }
    }

    for (int it = 0; it < 18; it++) {
        __syncthreads();                  // previous halo fully consumed
#pragma unroll
        for (int j = 0; j < 6; j++) {
            int t = tid + j * 256;
            if (t < 1296) {
                int p = t / 324, e = t % 324;
                halo[p * 360 + (e / 18) * 20 + (e % 18)] = pre[j];
            }
        }
        __syncthreads();
        if (it + 1 < 18) {
#pragma unroll
            for (int j = 0; j < 6; j++) {
                int t = tid + j * 256;
                if (t < 1296) {
                    int p = t / 324, e = t % 324;
                    int hr = e / 18, hc = e % 18;
                    int pi = (it + 1) * 4 + p;
                    int which = pi / 24, c = pi % 24;
                    int ch = which * CDIM + h * CD + c;
                    int Rg = r0 - 1 + hr, Cg = c0 - 1 + hc;
                    float vv = 0.f;
                    if (Rg >= 0 && Rg < HS && Cg >= 0 && Cg < WS)
                        vv = g_qkv0[bq + (size_t)ch * NPIX + (size_t)Rg * WS + Cg];
                    pre[j] = vv;
                }
            }
        }

        const int pi = it * 4 + slot;
        const int which = pi / 24, c = pi % 24;
        const int ch = which * CDIM + h * CD + c;
        const float* wp = w_dw + ch * 9;
        const float* hp = halo + slot * 360;
        float bz = __ldg(&b_dw[ch]);
        float s0 = bz, s1 = bz, s2 = bz, s3 = bz;
#pragma unroll
        for (int r = 0; r < 3; r++) {
            float4 a = *(const float4*)(hp + (sr + r) * 20 + sc);
            float4 bv = *(const float4*)(hp + (sr + r) * 20 + sc + 4);
            float w0 = __ldg(&wp[r * 3 + 0]);
            float w1 = __ldg(&wp[r * 3 + 1]);
            float w2 = __ldg(&wp[r * 3 + 2]);
            s0 += a.x * w0 + a.y * w1 + a.z * w2;
            s1 += a.y * w0 + a.z * w1 + a.w * w2;
            s2 += a.z * w0 + a.w * w1 + bv.x * w2;
            s3 += a.w * w0 + bv.x * w1 + bv.y * w2;
        }
        const int p = sr * 16 + sc;
        if (which == 0) {
            qs[(p + 0) * 25 + c] = s0;
            qs[(p + 1) * 25 + c] = s1;
            qs[(p + 2) * 25 + c] = s2;
            qs[(p + 3) * 25 + c] = s3;
        } else if (which == 1) {
            ks2[(p + 0) * 25 + c] = s0;
            ks2[(p + 1) * 25 + c] = s1;
            ks2[(p + 2) * 25 + c] = s2;
            ks2[(p + 3) * 25 + c] = s3;
        } else {
            float* vp = g_v + (size_t)b * CDIM * NPIX + (size_t)(h * CD + c) * NPIX
                        + (size_t)(r0 + sr) * WS + (c0 + sc);
            *(float4*)vp = make_float4(s0, s1, s2, s3);
        }
    }
    __syncthreads();

    const int bh = b * HEADS + h;
    if (tid < 192) {
        const int cc = tid >> 3;
        const int db = (tid & 7) * 3;
        float a0 = 0.f, a1 = 0.f, a2 = 0.f;
        for (int p = 0; p < 256; p++) {
            float qv = qs[p * 25 + cc];
            a0 += qv * ks2[p * 25 + db];
            a1 += qv * ks2[p * 25 + db + 1];
            a2 += qv * ks2[p * 25 + db + 2];
        }
        float* Gp = g_G + (size_t)bh * CD * CD + cc * CD + db;
        atomicAdd(&Gp[0], a0);
        atomicAdd(&Gp[1], a1);
        atomicAdd(&Gp[2], a2);
    } else if (tid < 216) {
        const int c = tid - 192;
        float a = 0.f;
        for (int p = 0; p < 256; p++) { float qv = qs[p * 25 + c]; a += qv * qv; }
        atomicAdd(&g_QN[bh * CD + c], a);
    } else if (tid < 240) {
        const int c = tid - 216;
        float a = 0.f;
        for (int p = 0; p < 256; p++) { float kv = ks2[p * 25 + c]; a += kv * kv; }
        atomicAdd(&g_KN[bh * CD + c], a);
    }
}

// ---------------- attn: norms + 4x top-k sparse softmax via rank selection -> g_W ----------------
__global__ __launch_bounds__(32) void attn_kernel(
    const float* __restrict__ temp,
    const float* __restrict__ a1, const float* __restrict__ a2,
    const float* __restrict__ a3, const float* __restrict__ a4)
{
    const int bh = blockIdx.x;
    const int h = bh % HEADS;
    const int c = threadIdx.x;
    if (c >= CD) return;
    float attn[CD];
    float qn = fmaxf(sqrtf(g_QN[bh * CD + c]), 1e-12f);
    const float tmp = temp[h];
#pragma unroll
    for (int j = 0; j < CD; j++) {
        float kn = fmaxf(sqrtf(g_KN[bh * CD + j]), 1e-12f);
        attn[j] = g_G[(size_t)bh * CD * CD + c * CD + j] * tmp / (qn * kn);
    }
    float m = attn[0];
#pragma unroll
    for (int j = 1; j < CD; j++) m = fmaxf(m, attn[j]);
    int rank[CD];
#pragma unroll
    for (int j = 0; j < CD; j++) {
        int r = 0;
#pragma unroll
        for (int i = 0; i < CD; i++) {
            bool gt = (attn[i] > attn[j]) || (attn[i] == attn[j] && i < j);
            r += gt ? 1 : 0;
        }
        rank[j] = r;
    }
    float e[CD];
    float sum0 = 0.f, sum1 = 0.f, sum2 = 0.f, sum3 = 0.f;
#pragma unroll
    for (int j = 0; j < CD; j++) {
        e[j] = expf(attn[j] - m);
        if (rank[j] < 12) sum0 += e[j];
        if (rank[j] < 16) sum1 += e[j];
        if (rank[j] < 18) sum2 += e[j];
        if (rank[j] < 19) sum3 += e[j];
    }
    const float r0 = a1[0] / sum0, r1 = a2[0] / sum1, r2 = a3[0] / sum2, r3 = a4[0] / sum3;
    float* Wp = g_W + (size_t)bh * CD * CD + c * CD;
#pragma unroll
    for (int j = 0; j < CD; j++) {
        float w = 0.f;
        if (rank[j] < 12) w += r0 * e[j];
        if (rank[j] < 16) w += r1 * e[j];
        if (rank[j] < 18) w += r2 * e[j];
        if (rank[j] < 19) w += r3 * e[j];
        Wp[j] = w;
    }
}

// ---------------- fold: M[b][o][h*24+d] = sum_c wproj[o][h*24+c] * W[b,h][c][d] ----------------
__global__ __launch_bounds__(256) void fold_kernel(const float* __restrict__ wproj)
{
    const int b = blockIdx.x, s = blockIdx.y;
    const int t = threadIdx.x;
    const int o = s * 32 + (t >> 3);
    const int hh = t & 7;
    const float* Wp = g_W + ((size_t)(b * HEADS + hh)) * CD * CD;
    float acc[CD];
#pragma unroll
    for (int d = 0; d < CD; d++) acc[d] = 0.f;
#pragma unroll
    for (int c = 0; c < CD; c++) {
        float w = __ldg(&wproj[o * CDIM + hh * CD + c]);
#pragma unroll
        for (int d = 0; d < CD; d++) acc[d] += w * __ldg(&Wp[c * CD + d]);
    }
    float* Mo = g_M + (size_t)b * CDIM * CDIM + (size_t)o * CDIM + hh * CD;
#pragma unroll
    for (int d = 0; d < CD; d++) Mo[d] = acc[d];
}

// ---------------- launch (R14 schedule) ----------------
extern "C" void kernel_launch(void* const* d_in, const int* in_sizes, int n_in,
                              void* d_out, int out_size)
{
    const float* x      = (const float*)d_in[0];
    const float* w_qkv  = (const float*)d_in[1];
    const float* b_qkv  = (const float*)d_in[2];
    const float* w_dw   = (const float*)d_in[3];
    const float* b_dw   = (const float*)d_in[4];
    const float* w_proj = (const float*)d_in[5];
    const float* b_proj = (const float*)d_in[6];
    const float* temp   = (const float*)d_in[7];
    const float* a1     = (const float*)d_in[8];
    const float* a2     = (const float*)d_in[9];
    const float* a3     = (const float*)d_in[10];
    const float* a4     = (const float*)d_in[11];
    float* out = (float*)d_out;

    cudaFuncSetAttribute(dw_gram_kernel, cudaFuncAttributeMaxDynamicSharedMemorySize, DW_SMEM_FLOATS * 4);

    init_stats_kernel<<<64, 256>>>();

    // qkv 1x1 conv: g_qkv0[b] = w_qkv @ x[b] + b_qkv
    gemm_kernel<0><<<dim3(NPIX / 128, C3 / 64, BATCH), 128>>>(w_qkv, x, b_qkv, nullptr);

    // dw conv + gram
    dw_gram_kernel<<<dim3(64, HEADS, BATCH), 256, DW_SMEM_FLOATS * 4>>>(w_dw, b_dw);

    // attention weights + fold
    attn_kernel<<<BATCH * HEADS, 32>>>(temp, a1, a2, a3, a4);
    fold_kernel<<<dim3(BATCH, 6), 256>>>(w_proj);

    // out[b] = g_M[b] @ g_v[b] + b_proj
    gemm_kernel<1><<<dim3(NPIX / 128, CDIM / 64, BATCH), 128>>>(nullptr, nullptr, b_proj, out);
}

// round 17
// speedup vs baseline: 1.2780x; 1.0427x over previous
#include <cuda_runtime.h>
#include <cuda_pipeline.h>
#include <cstdint>

#define HS 128
#define WS 128
#define NPIX 16384
#define BATCH 8
#define CDIM 192
#define C3 576
#define HEADS 8
#define CD 24

// ---------------- scratch (device globals; no allocation allowed) ----------------
__device__ __align__(128) float g_qkv0[(size_t)BATCH * C3 * NPIX];   // after 1x1 conv
__device__ __align__(128) float g_v[(size_t)BATCH * CDIM * NPIX];    // v after dw conv
__device__ __align__(128) float g_G[BATCH * HEADS * CD * CD];
__device__ __align__(128) float g_QN[BATCH * HEADS * CD];
__device__ __align__(128) float g_KN[BATCH * HEADS * CD];
__device__ __align__(128) float g_W[BATCH * HEADS * CD * CD];
__device__ __align__(128) float g_M[BATCH * CDIM * CDIM];

// ---------------- init ----------------
__global__ void init_stats_kernel() {
    int stride = gridDim.x * blockDim.x;
    int i = blockIdx.x * blockDim.x + threadIdx.x;
    for (; i < BATCH * HEADS * CD * CD; i += stride) g_G[i] = 0.f;
    int j = blockIdx.x * blockDim.x + threadIdx.x;
    for (; j < BATCH * HEADS * CD; j += stride) { g_QN[j] = 0.f; g_KN[j] = 0.f; }
}

// ---------------- SGEMM, cp.async double-buffered + conflict-free fragments ----------------
// MODE 0: A = w_qkv (576x192), B = x[b] (192xN), C = g_qkv0[b]
// MODE 1: A = g_M[b] (192x192), B = g_v[b] (192xN), C = out[b]
// BM=64, BN=128, BK=16, TM=TN=8 (2x4 split halves), 128 threads.
template<int MODE>
__global__ __launch_bounds__(128) void gemm_kernel(
    const float* __restrict__ Aext, const float* __restrict__ Bext,
    const float* __restrict__ bias, float* __restrict__ Cext)
{
    constexpr int K = CDIM;
    const int b = blockIdx.z;
    const float* Ab = (MODE == 0) ? Aext : (g_M + (size_t)b * CDIM * CDIM);
    const float* Bb = (MODE == 0) ? (Bext + (size_t)b * CDIM * NPIX)
                                  : (g_v + (size_t)b * CDIM * NPIX);
    float* Cb = (MODE == 0) ? (g_qkv0 + (size_t)b * C3 * NPIX)
                            : (Cext + (size_t)b * CDIM * NPIX);

    const int n0 = blockIdx.x * 128;
    const int m0 = blockIdx.y * 64;

    __shared__ __align__(16) float As[2][16][64];
    __shared__ __align__(16) float Bs[2][16][128];

    const int tid = threadIdx.x;
    const int tx = tid & 15;        // 0..15 -> n quads
    const int ty = tid >> 4;        // 0..7  -> m quads

    const int arow = tid >> 1;            // 0..63
    const int acol = (tid & 1) * 8;       // 0 or 8
    const int bkk = tid >> 5;             // base kk for this thread's 4 B chunks
    const int bc4 = (tid & 31) * 4;       // col within row

    float acc[8][8];
#pragma unroll
    for (int i = 0; i < 8; i++)
#pragma unroll
        for (int j = 0; j < 8; j++) acc[i][j] = 0.f;

    // prologue: stage slab 0 into buffer 0
    {
        float4 av0 = *(const float4*)&Ab[(size_t)(m0 + arow) * K + acol];
        float4 av1 = *(const float4*)&Ab[(size_t)(m0 + arow) * K + acol + 4];
        As[0][acol + 0][arow] = av0.x;
        As[0][acol + 1][arow] = av0.y;
        As[0][acol + 2][arow] = av0.z;
        As[0][acol + 3][arow] = av0.w;
        As[0][acol + 4][arow] = av1.x;
        As[0][acol + 5][arow] = av1.y;
        As[0][acol + 6][arow] = av1.z;
        As[0][acol + 7][arow] = av1.w;
#pragma unroll
        for (int i = 0; i < 4; i++) {
            int kk = bkk + i * 4;
            __pipeline_memcpy_async(&Bs[0][kk][bc4],
                                    &Bb[(size_t)kk * NPIX + n0 + bc4], 16);
        }
        __pipeline_commit();
    }
    __pipeline_wait_prior(0);
    __syncthreads();

    int buf = 0;
#pragma unroll 1
    for (int s = 0; s < K / 16; s++) {
        const int k1 = (s + 1) * 16;
        float4 av0, av1;
        if (k1 < K) {
            // issue next slab: A LDG held in regs, B via cp.async into buf^1
            av0 = *(const float4*)&Ab[(size_t)(m0 + arow) * K + k1 + acol];
            av1 = *(const float4*)&Ab[(size_t)(m0 + arow) * K + k1 + acol + 4];
#pragma unroll
            for (int i = 0; i < 4; i++) {
                int kk = bkk + i * 4;
                __pipeline_memcpy_async(&Bs[buf ^ 1][kk][bc4],
                                        &Bb[(size_t)(k1 + kk) * NPIX + n0 + bc4], 16);
            }
            __pipeline_commit();
        }
#pragma unroll
        for (int kk = 0; kk < 16; kk++) {
            float ra[8], rb[8];
            *(float4*)&ra[0] = *(const float4*)&As[buf][kk][ty * 4];
            *(float4*)&ra[4] = *(const float4*)&As[buf][kk][32 + ty * 4];
            *(float4*)&rb[0] = *(const float4*)&Bs[buf][kk][tx * 4];
            *(float4*)&rb[4] = *(const float4*)&Bs[buf][kk][64 + tx * 4];
#pragma unroll
            for (int i = 0; i < 8; i++)
#pragma unroll
                for (int j = 0; j < 8; j++) acc[i][j] += ra[i] * rb[j];
        }
        if (k1 < K) {
            int nb = buf ^ 1;
            As[nb][acol + 0][arow] = av0.x;
            As[nb][acol + 1][arow] = av0.y;
            As[nb][acol + 2][arow] = av0.z;
            As[nb][acol + 3][arow] = av0.w;
            As[nb][acol + 4][arow] = av1.x;
            As[nb][acol + 5][arow] = av1.y;
            As[nb][acol + 6][arow] = av1.z;
            As[nb][acol + 7][arow] = av1.w;
            __pipeline_wait_prior(0);
        }
        __syncthreads();
        buf ^= 1;
    }

    // epilogue: row half mh -> m0 + mh*32 + ty*4 + i; col half -> n0 + nh*64 + tx*4
#pragma unroll
    for (int mh = 0; mh < 2; mh++) {
#pragma unroll
        for (int i = 0; i < 4; i++) {
            int o = m0 + mh * 32 + ty * 4 + i;
            float bo = bias[o];
            size_t base = (size_t)o * NPIX + n0;
            int ai = mh * 4 + i;
            float4 v0 = make_float4(acc[ai][0] + bo, acc[ai][1] + bo, acc[ai][2] + bo, acc[ai][3] + bo);
            float4 v1 = make_float4(acc[ai][4] + bo, acc[ai][5] + bo, acc[ai][6] + bo, acc[ai][7] + bo);
            *(float4*)&Cb[base + tx * 4] = v0;
            *(float4*)&Cb[base + 64 + tx * 4] = v1;
        }
    }
}

// ---------------- dw conv (3x3) + Gram/norm reduction + v write (R14-verbatim) ----------------
#define DW_QS 0                      // 256*25 floats
#define DW_KS 6400                   // 256*25 floats
#define DW_HALO 12800                // 4 * 360 floats = 1440
#define DW_SMEM_FLOATS 14240         // * 4 = 56960 bytes

__global__ __launch_bounds__(256) void dw_gram_kernel(
    const float* __restrict__ w_dw, const float* __restrict__ b_dw)
{
    extern __shared__ float ds[];
    float* qs = ds + DW_QS;          // [pix 0..255][25]
    float* ks2 = ds + DW_KS;
    float* halo = ds + DW_HALO;      // [slot][18 rows][20 cols]

    const int b = blockIdx.z, h = blockIdx.y, tile = blockIdx.x;
    const int r0 = (tile >> 3) * 16, c0 = (tile & 7) * 16;
    const int tid = threadIdx.x;
    const int slot = tid >> 6;           // 0..3
    const int s = tid & 63;
    const int sr = s >> 2;               // 0..15 output row
    const int sc = (s & 3) * 4;          // 0,4,8,12 output col base
    const size_t bq = (size_t)b * C3 * NPIX;

    float pre[6];
#pragma unroll
    for (int j = 0; j < 6; j++) {
        int t = tid + j * 256;
        if (t < 1296) {
            int p = t / 324, e = t % 324;
            int hr = e / 18, hc = e % 18;
            int pi = p;                       // it = 0
            int which = pi / 24, c = pi % 24;
            int ch = which * CDIM + h * CD + c;
            int Rg = r0 - 1 + hr, Cg = c0 - 1 + hc;
            float vv = 0.f;
            if (Rg >= 0 && Rg < HS && Cg >= 0 && Cg < WS)
                vv = g_qkv0[bq + (size_t)ch * NPIX + (size_t)Rg * WS + Cg];
            pre[j] = vv;
        }
    }

    for (int it = 0; it < 18; it++) {
        __syncthreads();                  // previous halo fully consumed
#pragma unroll
        for (int j = 0; j < 6; j++) {
            int t = tid + j * 256;
            if (t < 1296) {
                int p = t / 324, e = t % 324;
                halo[p * 360 + (e / 18) * 20 + (e % 18)] = pre[j];
            }
        }
        __syncthreads();
        if (it + 1 < 18) {
#pragma unroll
            for (int j = 0; j < 6; j++) {
                int t = tid + j * 256;
                if (t < 1296) {
                    int p = t / 324, e = t % 324;
                    int hr = e / 18, hc = e % 18;
                    int pi = (it + 1) * 4 + p;
                    int which = pi / 24, c = pi % 24;
                    int ch = which * CDIM + h * CD + c;
                    int Rg = r0 - 1 + hr, Cg = c0 - 1 + hc;
                    float vv = 0.f;
                    if (Rg >= 0 && Rg < HS && Cg >= 0 && Cg < WS)
                        vv = g_qkv0[bq + (size_t)ch * NPIX + (size_t)Rg * WS + Cg];
                    pre[j] = vv;
                }
            }
        }

        const int pi = it * 4 + slot;
        const int which = pi / 24, c = pi % 24;
        const int ch = which * CDIM + h * CD + c;
        const float* wp = w_dw + ch * 9;
        const float* hp = halo + slot * 360;
        float bz = __ldg(&b_dw[ch]);
        float s0 = bz, s1 = bz, s2 = bz, s3 = bz;
#pragma unroll
        for (int r = 0; r < 3; r++) {
            float4 a = *(const float4*)(hp + (sr + r) * 20 + sc);
            float4 bv = *(const float4*)(hp + (sr + r) * 20 + sc + 4);
            float w0 = __ldg(&wp[r * 3 + 0]);
            float w1 = __ldg(&wp[r * 3 + 1]);
            float w2 = __ldg(&wp[r * 3 + 2]);
            s0 += a.x * w0 + a.y * w1 + a.z * w2;
            s1 += a.y * w0 + a.z * w1 + a.w * w2;
            s2 += a.z * w0 + a.w * w1 + bv.x * w2;
            s3 += a.w * w0 + bv.x * w1 + bv.y * w2;
        }
        const int p = sr * 16 + sc;
        if (which == 0) {
            qs[(p + 0) * 25 + c] = s0;
            qs[(p + 1) * 25 + c] = s1;
            qs[(p + 2) * 25 + c] = s2;
            qs[(p + 3) * 25 + c] = s3;
        } else if (which == 1) {
            ks2[(p + 0) * 25 + c] = s0;
            ks2[(p + 1) * 25 + c] = s1;
            ks2[(p + 2) * 25 + c] = s2;
            ks2[(p + 3) * 25 + c] = s3;
        } else {
            float* vp = g_v + (size_t)b * CDIM * NPIX + (size_t)(h * CD + c) * NPIX
                        + (size_t)(r0 + sr) * WS + (c0 + sc);
            *(float4*)vp = make_float4(s0, s1, s2, s3);
        }
    }
    __syncthreads();

    const int bh = b * HEADS + h;
    if (tid < 192) {
        const int cc = tid >> 3;
        const int db = (tid & 7) * 3;
        float a0 = 0.f, a1 = 0.f, a2 = 0.f;
        for (int p = 0; p < 256; p++) {
            float qv = qs[p * 25 + cc];
            a0 += qv * ks2[p * 25 + db];
            a1 += qv * ks2[p * 25 + db + 1];
            a2 += qv * ks2[p * 25 + db + 2];
        }
        float* Gp = g_G + (size_t)bh * CD * CD + cc * CD + db;
        atomicAdd(&Gp[0], a0);
        atomicAdd(&Gp[1], a1);
        atomicAdd(&Gp[2], a2);
    } else if (tid < 216) {
        const int c = tid - 192;
        float a = 0.f;
        for (int p = 0; p < 256; p++) { float qv = qs[p * 25 + c]; a += qv * qv; }
        atomicAdd(&g_QN[bh * CD + c], a);
    } else if (tid < 240) {
        const int c = tid - 216;
        float a = 0.f;
        for (int p = 0; p < 256; p++) { float kv = ks2[p * 25 + c]; a += kv * kv; }
        atomicAdd(&g_KN[bh * CD + c], a);
    }
}

// ---------------- attn: norms + 4x top-k sparse softmax via rank selection -> g_W ----------------
__global__ __launch_bounds__(32) void attn_kernel(
    const float* __restrict__ temp,
    const float* __restrict__ a1, const float* __restrict__ a2,
    const float* __restrict__ a3, const float* __restrict__ a4)
{
    const int bh = blockIdx.x;
    const int h = bh % HEADS;
    const int c = threadIdx.x;
    if (c >= CD) return;
    float attn[CD];
    float qn = fmaxf(sqrtf(g_QN[bh * CD + c]), 1e-12f);
    const float tmp = temp[h];
#pragma unroll
    for (int j = 0; j < CD; j++) {
        float kn = fmaxf(sqrtf(g_KN[bh * CD + j]), 1e-12f);
        attn[j] = g_G[(size_t)bh * CD * CD + c * CD + j] * tmp / (qn * kn);
    }
    float m = attn[0];
#pragma unroll
    for (int j = 1; j < CD; j++) m = fmaxf(m, attn[j]);
    int rank[CD];
#pragma unroll
    for (int j = 0; j < CD; j++) {
        int r = 0;
#pragma unroll
        for (int i = 0; i < CD; i++) {
            bool gt = (attn[i] > attn[j]) || (attn[i] == attn[j] && i < j);
            r += gt ? 1 : 0;
        }
        rank[j] = r;
    }
    float e[CD];
    float sum0 = 0.f, sum1 = 0.f, sum2 = 0.f, sum3 = 0.f;
#pragma unroll
    for (int j = 0; j < CD; j++) {
        e[j] = expf(attn[j] - m);
        if (rank[j] < 12) sum0 += e[j];
        if (rank[j] < 16) sum1 += e[j];
        if (rank[j] < 18) sum2 += e[j];
        if (rank[j] < 19) sum3 += e[j];
    }
    const float r0 = a1[0] / sum0, r1 = a2[0] / sum1, r2 = a3[0] / sum2, r3 = a4[0] / sum3;
    float* Wp = g_W + (size_t)bh * CD * CD + c * CD;
#pragma unroll
    for (int j = 0; j < CD; j++) {
        float w = 0.f;
        if (rank[j] < 12) w += r0 * e[j];
        if (rank[j] < 16) w += r1 * e[j];
        if (rank[j] < 18) w += r2 * e[j];
        if (rank[j] < 19) w += r3 * e[j];
        Wp[j] = w;
    }
}

// ---------------- fold: M[b][o][h*24+d] = sum_c wproj[o][h*24+c] * W[b,h][c][d] ----------------
__global__ __launch_bounds__(256) void fold_kernel(const float* __restrict__ wproj)
{
    const int b = blockIdx.x, s = blockIdx.y;
    const int t = threadIdx.x;
    const int o = s * 32 + (t >> 3);
    const int hh = t & 7;
    const float* Wp = g_W + ((size_t)(b * HEADS + hh)) * CD * CD;
    float acc[CD];
#pragma unroll
    for (int d = 0; d < CD; d++) acc[d] = 0.f;
#pragma unroll
    for (int c = 0; c < CD; c++) {
        float w = __ldg(&wproj[o * CDIM + hh * CD + c]);
#pragma unroll
        for (int d = 0; d < CD; d++) acc[d] += w * __ldg(&Wp[c * CD + d]);
    }
    float* Mo = g_M + (size_t)b * CDIM * CDIM + (size_t)o * CDIM + hh * CD;
#pragma unroll
    for (int d = 0; d < CD; d++) Mo[d] = acc[d];
}

// ---------------- launch (R14 schedule) ----------------
extern "C" void kernel_launch(void* const* d_in, const int* in_sizes, int n_in,
                              void* d_out, int out_size)
{
    const float* x      = (const float*)d_in[0];
    const float* w_qkv  = (const float*)d_in[1];
    const float* b_qkv  = (const float*)d_in[2];
    const float* w_dw   = (const float*)d_in[3];
    const float* b_dw   = (const float*)d_in[4];
    const float* w_proj = (const float*)d_in[5];
    const float* b_proj = (const float*)d_in[6];
    const float* temp   = (const float*)d_in[7];
    const float* a1     = (const float*)d_in[8];
    const float* a2     = (const float*)d_in[9];
    const float* a3     = (const float*)d_in[10];
    const float* a4     = (const float*)d_in[11];
    float* out = (float*)d_out;

    cudaFuncSetAttribute(dw_gram_kernel, cudaFuncAttributeMaxDynamicSharedMemorySize, DW_SMEM_FLOATS * 4);

    init_stats_kernel<<<64, 256>>>();

    // qkv 1x1 conv: g_qkv0[b] = w_qkv @ x[b] + b_qkv
    gemm_kernel<0><<<dim3(NPIX / 128, C3 / 64, BATCH), 128>>>(w_qkv, x, b_qkv, nullptr);

    // dw conv + gram
    dw_gram_kernel<<<dim3(64, HEADS, BATCH), 256, DW_SMEM_FLOATS * 4>>>(w_dw, b_dw);

    // attention weights + fold
    attn_kernel<<<BATCH * HEADS, 32>>>(temp, a1, a2, a3, a4);
    fold_kernel<<<dim3(BATCH, 6), 256>>>(w_proj);

    // out[b] = g_M[b] @ g_v[b] + b_proj
    gemm_kernel<1><<<dim3(NPIX / 128, CDIM / 64, BATCH), 128>>>(nullptr, nullptr, b_proj, out);
}